// round 1
// baseline (speedup 1.0000x reference)
#include <cuda_runtime.h>
#include <cuda_bf16.h>

// Problem constants
#define SEQ     2048
#define HIDDEN  2048
#define HEADS   32
#define GROUPS  8
#define HEAD_D  64
#define KV_DIM  512   // GROUPS * HEAD_D
#define QPG     4     // HEADS / GROUPS

// Scratch (device globals: no allocation allowed)
__device__ float g_Q[SEQ * HIDDEN];
__device__ float g_K[SEQ * KV_DIM];
__device__ float g_V[SEQ * KV_DIM];
__device__ float g_A[SEQ * HIDDEN];   // attention output, [s, h*64+d]

// ---------------------------------------------------------------------------
// SGEMM with bias: C[M,N] = A[M,K] @ B[K,N] + bias[N]
// 128x128 block, BK=8, 256 threads, 8x8 per-thread microtile.
// M,N,K assumed multiples of tile dims (true here: 2048/512).
// ---------------------------------------------------------------------------
__global__ __launch_bounds__(256) void sgemm_bias_kernel(
    const float* __restrict__ A, const float* __restrict__ B,
    const float* __restrict__ bias, float* __restrict__ C,
    int M, int N, int K)
{
    const int BK = 8;
    __shared__ float As[BK][128];
    __shared__ float Bs[BK][128];

    int tid = threadIdx.x;
    int bx = blockIdx.x, by = blockIdx.y;
    int tx = tid & 15;        // 0..15  -> N direction
    int ty = tid >> 4;        // 0..15  -> M direction

    // load mapping
    int aRow = tid >> 1;            // 0..127
    int aCol = (tid & 1) * 4;       // 0 or 4
    int bRow = tid >> 5;            // 0..7
    int bCol = (tid & 31) * 4;      // 0..124

    const float* Ablk = A + (size_t)by * 128 * K;
    const float* Bblk = B + (size_t)bx * 128;

    float acc[8][8];
#pragma unroll
    for (int i = 0; i < 8; i++)
#pragma unroll
        for (int j = 0; j < 8; j++) acc[i][j] = 0.f;

    for (int kt = 0; kt < K; kt += BK) {
        float4 a4 = *(const float4*)&Ablk[(size_t)aRow * K + kt + aCol];
        As[aCol + 0][aRow] = a4.x;
        As[aCol + 1][aRow] = a4.y;
        As[aCol + 2][aRow] = a4.z;
        As[aCol + 3][aRow] = a4.w;
        float4 b4 = *(const float4*)&Bblk[(size_t)(kt + bRow) * N + bCol];
        *(float4*)&Bs[bRow][bCol] = b4;
        __syncthreads();

#pragma unroll
        for (int k = 0; k < BK; k++) {
            float ra[8], rb[8];
#pragma unroll
            for (int i = 0; i < 8; i++) ra[i] = As[k][ty * 8 + i];
#pragma unroll
            for (int j = 0; j < 8; j++) rb[j] = Bs[k][tx * 8 + j];
#pragma unroll
            for (int i = 0; i < 8; i++)
#pragma unroll
                for (int j = 0; j < 8; j++)
                    acc[i][j] += ra[i] * rb[j];
        }
        __syncthreads();
    }

#pragma unroll
    for (int i = 0; i < 8; i++) {
        int row = by * 128 + ty * 8 + i;
#pragma unroll
        for (int j = 0; j < 8; j += 4) {
            int col = bx * 128 + tx * 8 + j;
            float4 o;
            o.x = acc[i][j + 0] + bias[col + 0];
            o.y = acc[i][j + 1] + bias[col + 1];
            o.z = acc[i][j + 2] + bias[col + 2];
            o.w = acc[i][j + 3] + bias[col + 3];
            *(float4*)&C[(size_t)row * N + col] = o;
        }
    }
}

// ---------------------------------------------------------------------------
// Flash attention (causal, GQA). grid = (SEQ/64, HEADS), block = 64 threads.
// Thread t owns query row qblk*64 + t of head h: q and o rows live in
// registers; 16-key K/V tiles staged through smem; online softmax.
// ---------------------------------------------------------------------------
__global__ __launch_bounds__(64) void flash_attn_kernel(
    const float* __restrict__ Q, const float* __restrict__ K,
    const float* __restrict__ V, float* __restrict__ O)
{
    int qblk = blockIdx.x;
    int h    = blockIdx.y;
    int g    = h / QPG;
    int row  = qblk * 64 + threadIdx.x;  // global query index

    const float* qp = Q + (size_t)row * HIDDEN + h * HEAD_D;
    float q[HEAD_D];
#pragma unroll
    for (int d = 0; d < HEAD_D; d += 4) {
        float4 v4 = *(const float4*)&qp[d];
        q[d + 0] = v4.x * 0.125f;   // 1/sqrt(64)
        q[d + 1] = v4.y * 0.125f;
        q[d + 2] = v4.z * 0.125f;
        q[d + 3] = v4.w * 0.125f;
    }

    float o[HEAD_D];
#pragma unroll
    for (int d = 0; d < HEAD_D; d++) o[d] = 0.f;
    float m = -1e30f, l = 0.f;

    __shared__ float ks[16][HEAD_D];
    __shared__ float vs[16][HEAD_D];

    int kmax = qblk * 64 + 63;   // last key any row of this block can see
    int ldr = threadIdx.x >> 2;          // key row 0..15
    int ldc = (threadIdx.x & 3) * 16;    // col start

    for (int j0 = 0; j0 <= kmax; j0 += 16) {
        const float* kp = K + (size_t)(j0 + ldr) * KV_DIM + g * HEAD_D + ldc;
        const float* vp = V + (size_t)(j0 + ldr) * KV_DIM + g * HEAD_D + ldc;
#pragma unroll
        for (int i = 0; i < 16; i += 4) {
            *(float4*)&ks[ldr][ldc + i] = *(const float4*)&kp[i];
            *(float4*)&vs[ldr][ldc + i] = *(const float4*)&vp[i];
        }
        __syncthreads();

        // scores for 16 keys
        float s[16];
#pragma unroll
        for (int j = 0; j < 16; j++) {
            float acc = 0.f;
#pragma unroll
            for (int d = 0; d < HEAD_D; d += 4) {
                float4 k4 = *(const float4*)&ks[j][d];
                acc += q[d + 0] * k4.x;
                acc += q[d + 1] * k4.y;
                acc += q[d + 2] * k4.z;
                acc += q[d + 3] * k4.w;
            }
            s[j] = (j0 + j <= row) ? acc : -1e30f;
        }

        float mc = m;
#pragma unroll
        for (int j = 0; j < 16; j++) mc = fmaxf(mc, s[j]);
        float scaleOld = __expf(m - mc);
        float lsum = 0.f;
#pragma unroll
        for (int j = 0; j < 16; j++) {
            s[j] = __expf(s[j] - mc);   // p_j
            lsum += s[j];
        }
        l = l * scaleOld + lsum;
#pragma unroll
        for (int d = 0; d < HEAD_D; d++) o[d] *= scaleOld;
#pragma unroll
        for (int j = 0; j < 16; j++) {
            float pj = s[j];
#pragma unroll
            for (int d = 0; d < HEAD_D; d += 4) {
                float4 v4 = *(const float4*)&vs[j][d];
                o[d + 0] += pj * v4.x;
                o[d + 1] += pj * v4.y;
                o[d + 2] += pj * v4.z;
                o[d + 3] += pj * v4.w;
            }
        }
        m = mc;
        __syncthreads();
    }

    float inv = 1.f / l;
    float* op = O + (size_t)row * HIDDEN + h * HEAD_D;
#pragma unroll
    for (int d = 0; d < HEAD_D; d += 4) {
        float4 v4;
        v4.x = o[d + 0] * inv;
        v4.y = o[d + 1] * inv;
        v4.z = o[d + 2] * inv;
        v4.w = o[d + 3] * inv;
        *(float4*)&op[d] = v4;
    }
}

// ---------------------------------------------------------------------------
extern "C" void kernel_launch(void* const* d_in, const int* in_sizes, int n_in,
                              void* d_out, int out_size)
{
    const float* x  = (const float*)d_in[0];
    // d_in[1] = causal_mask (handled analytically)
    const float* Wq = (const float*)d_in[2];
    const float* bq = (const float*)d_in[3];
    const float* Wk = (const float*)d_in[4];
    const float* bk = (const float*)d_in[5];
    const float* Wv = (const float*)d_in[6];
    const float* bv = (const float*)d_in[7];
    const float* Wo = (const float*)d_in[8];
    const float* bo = (const float*)d_in[9];
    float* out = (float*)d_out;

    float* Qb; cudaGetSymbolAddress((void**)&Qb, g_Q);
    float* Kb; cudaGetSymbolAddress((void**)&Kb, g_K);
    float* Vb; cudaGetSymbolAddress((void**)&Vb, g_V);
    float* Ab; cudaGetSymbolAddress((void**)&Ab, g_A);

    dim3 blk(256);
    // Q = x @ Wq + bq   [2048, 2048]
    sgemm_bias_kernel<<<dim3(HIDDEN / 128, SEQ / 128), blk>>>(x, Wq, bq, Qb, SEQ, HIDDEN, HIDDEN);
    // K = x @ Wk + bk   [2048, 512]
    sgemm_bias_kernel<<<dim3(KV_DIM / 128, SEQ / 128), blk>>>(x, Wk, bk, Kb, SEQ, KV_DIM, HIDDEN);
    // V = x @ Wv + bv   [2048, 512]
    sgemm_bias_kernel<<<dim3(KV_DIM / 128, SEQ / 128), blk>>>(x, Wv, bv, Vb, SEQ, KV_DIM, HIDDEN);
    // attention
    flash_attn_kernel<<<dim3(SEQ / 64, HEADS), dim3(64)>>>(Qb, Kb, Vb, Ab);
    // out = A @ Wo + bo [2048, 2048]
    sgemm_bias_kernel<<<dim3(HIDDEN / 128, SEQ / 128), blk>>>(Ab, Wo, bo, out, SEQ, HIDDEN, HIDDEN);
}

// round 2
// speedup vs baseline: 1.6738x; 1.6738x over previous
#include <cuda_runtime.h>
#include <cuda_bf16.h>
#include <cstdint>

// Problem constants
#define SEQ     2048
#define HIDDEN  2048
#define HEADS   32
#define GROUPS  8
#define HEAD_D  64
#define KV_DIM  512   // GROUPS * HEAD_D
#define QPG     4     // HEADS / GROUPS

// Scratch (device globals: no allocation allowed)
__device__ float g_Q[SEQ * HIDDEN];
__device__ float g_K[SEQ * KV_DIM];
__device__ float g_V[SEQ * KV_DIM];
__device__ float g_A[SEQ * HIDDEN];   // attention output, [s, h*64+d]

// ---------------------------------------------------------------------------
// TF32 tensor-core GEMM with bias: C[M,N] = A[M,K] @ B[K,N] + bias[N]
// 128x128 block tile, BK=16, 256 threads (8 warps, 64x32 warp tile),
// mma.sync.m16n8k8.tf32, cp.async double-buffered smem.
// M,N multiples of 128; K multiple of 16 (true here).
// ---------------------------------------------------------------------------

__device__ __forceinline__ void cp_async16(uint32_t smem_addr, const void* gptr) {
    asm volatile("cp.async.cg.shared.global [%0], [%1], 16;\n"
                 :: "r"(smem_addr), "l"(gptr));
}
__device__ __forceinline__ void cp_async_commit() {
    asm volatile("cp.async.commit_group;\n" ::: "memory");
}
__device__ __forceinline__ void cp_async_wait1() {
    asm volatile("cp.async.wait_group 1;\n" ::: "memory");
}

__device__ __forceinline__ uint32_t f2tf32(float f) {
    uint32_t u;
    asm("cvt.rna.tf32.f32 %0, %1;\n" : "=r"(u) : "f"(f));
    return u;
}

// Smem layouts (padded for conflict-free fragment reads + 16B cp.async align):
//   As[stage][128 rows][20 cols]  (only cols 0..15 used)
//   Bs[stage][16 rows][136 cols]  (only cols 0..127 used)
#define AS_LD 20
#define BS_LD 136

__global__ __launch_bounds__(256) void tf32_gemm_bias_kernel(
    const float* __restrict__ A, const float* __restrict__ B,
    const float* __restrict__ bias, float* __restrict__ C,
    int M, int N, int K)
{
    __shared__ float As[2][128][AS_LD];
    __shared__ float Bs[2][16][BS_LD];

    const int tid   = threadIdx.x;
    const int warp  = tid >> 5;
    const int lane  = tid & 31;
    const int gid   = lane >> 2;   // group id 0..7
    const int tg    = lane & 3;    // thread-in-group 0..3

    const int warpM = warp & 1;    // 2 warp rows of 64
    const int warpN = warp >> 1;   // 4 warp cols of 32
    const int mBase = warpM * 64;
    const int nBase = warpN * 32;

    const int blockRow = blockIdx.y;   // M / 128
    const int blockCol = blockIdx.x;   // N / 128

    // Loader mapping: 512 float4 slots per tile; thread does slots tid, tid+256.
    // A slot s: row = s>>2 (0..127), colgroup = (s&3)*4
    // B slot s: row = s>>5 (0..15),  col = (s&31)*4
    const uint32_t asBase = (uint32_t)__cvta_generic_to_shared(&As[0][0][0]);
    const uint32_t bsBase = (uint32_t)__cvta_generic_to_shared(&Bs[0][0][0]);
    const uint32_t asStageBytes = 128 * AS_LD * 4;
    const uint32_t bsStageBytes = 16 * BS_LD * 4;

    const float* Ablk = A + (size_t)blockRow * 128 * K;
    const float* Bblk = B + (size_t)blockCol * 128;

    float acc[4][4][4];
#pragma unroll
    for (int i = 0; i < 4; i++)
#pragma unroll
        for (int j = 0; j < 4; j++)
#pragma unroll
            for (int r = 0; r < 4; r++) acc[i][j][r] = 0.f;

    const int T = K / 16;

    // --- tile loader (2 A-slots + 2 B-slots per thread) ---
    auto load_tile = [&](int stage, int kt) {
#pragma unroll
        for (int p = 0; p < 2; p++) {
            int s = tid + p * 256;
            {   // A
                int row = s >> 2;
                int col = (s & 3) * 4;
                uint32_t dst = asBase + stage * asStageBytes + (row * AS_LD + col) * 4;
                cp_async16(dst, &Ablk[(size_t)row * K + kt + col]);
            }
            {   // B
                int row = s >> 5;
                int col = (s & 31) * 4;
                uint32_t dst = bsBase + stage * bsStageBytes + (row * BS_LD + col) * 4;
                cp_async16(dst, &Bblk[(size_t)(kt + row) * N + col]);
            }
        }
    };

    load_tile(0, 0);
    cp_async_commit();

    for (int t = 0; t < T; t++) {
        if (t + 1 < T) load_tile((t + 1) & 1, (t + 1) * 16);
        cp_async_commit();          // possibly-empty group on last iter
        cp_async_wait1();           // tile t's group complete
        __syncthreads();

        const int st = t & 1;
#pragma unroll
        for (int kc = 0; kc < 16; kc += 8) {
            // A fragments: 4 m-tiles x 4 regs
            uint32_t af[4][4];
#pragma unroll
            for (int mt = 0; mt < 4; mt++) {
                int r0 = mBase + mt * 16 + gid;
                af[mt][0] = f2tf32(As[st][r0    ][kc + tg    ]);
                af[mt][1] = f2tf32(As[st][r0 + 8][kc + tg    ]);
                af[mt][2] = f2tf32(As[st][r0    ][kc + tg + 4]);
                af[mt][3] = f2tf32(As[st][r0 + 8][kc + tg + 4]);
            }
            // B fragments: 4 n-tiles x 2 regs
            uint32_t bf[4][2];
#pragma unroll
            for (int nt = 0; nt < 4; nt++) {
                int c0 = nBase + nt * 8 + gid;
                bf[nt][0] = f2tf32(Bs[st][kc + tg    ][c0]);
                bf[nt][1] = f2tf32(Bs[st][kc + tg + 4][c0]);
            }
#pragma unroll
            for (int mt = 0; mt < 4; mt++)
#pragma unroll
                for (int nt = 0; nt < 4; nt++) {
                    asm volatile(
                        "mma.sync.aligned.m16n8k8.row.col.f32.tf32.tf32.f32 "
                        "{%0,%1,%2,%3}, {%4,%5,%6,%7}, {%8,%9}, {%0,%1,%2,%3};\n"
                        : "+f"(acc[mt][nt][0]), "+f"(acc[mt][nt][1]),
                          "+f"(acc[mt][nt][2]), "+f"(acc[mt][nt][3])
                        : "r"(af[mt][0]), "r"(af[mt][1]), "r"(af[mt][2]), "r"(af[mt][3]),
                          "r"(bf[nt][0]), "r"(bf[nt][1]));
                }
        }
        __syncthreads();
    }

    // Epilogue: C = acc + bias
#pragma unroll
    for (int mt = 0; mt < 4; mt++) {
#pragma unroll
        for (int nt = 0; nt < 4; nt++) {
            int row = blockRow * 128 + mBase + mt * 16 + gid;
            int col = blockCol * 128 + nBase + nt * 8 + tg * 2;
            float bx = bias[col], by = bias[col + 1];
            float2 v0 = make_float2(acc[mt][nt][0] + bx, acc[mt][nt][1] + by);
            float2 v1 = make_float2(acc[mt][nt][2] + bx, acc[mt][nt][3] + by);
            *(float2*)&C[(size_t)row * N + col]       = v0;
            *(float2*)&C[(size_t)(row + 8) * N + col] = v1;
        }
    }
}

// ---------------------------------------------------------------------------
// Flash attention (causal, GQA). grid = (SEQ/64, HEADS), block = 64 threads.
// (unchanged from round 1)
// ---------------------------------------------------------------------------
__global__ __launch_bounds__(64) void flash_attn_kernel(
    const float* __restrict__ Q, const float* __restrict__ K,
    const float* __restrict__ V, float* __restrict__ O)
{
    int qblk = blockIdx.x;
    int h    = blockIdx.y;
    int g    = h / QPG;
    int row  = qblk * 64 + threadIdx.x;

    const float* qp = Q + (size_t)row * HIDDEN + h * HEAD_D;
    float q[HEAD_D];
#pragma unroll
    for (int d = 0; d < HEAD_D; d += 4) {
        float4 v4 = *(const float4*)&qp[d];
        q[d + 0] = v4.x * 0.125f;
        q[d + 1] = v4.y * 0.125f;
        q[d + 2] = v4.z * 0.125f;
        q[d + 3] = v4.w * 0.125f;
    }

    float o[HEAD_D];
#pragma unroll
    for (int d = 0; d < HEAD_D; d++) o[d] = 0.f;
    float m = -1e30f, l = 0.f;

    __shared__ float ks[16][HEAD_D];
    __shared__ float vs[16][HEAD_D];

    int kmax = qblk * 64 + 63;
    int ldr = threadIdx.x >> 2;
    int ldc = (threadIdx.x & 3) * 16;

    for (int j0 = 0; j0 <= kmax; j0 += 16) {
        const float* kp = K + (size_t)(j0 + ldr) * KV_DIM + g * HEAD_D + ldc;
        const float* vp = V + (size_t)(j0 + ldr) * KV_DIM + g * HEAD_D + ldc;
#pragma unroll
        for (int i = 0; i < 16; i += 4) {
            *(float4*)&ks[ldr][ldc + i] = *(const float4*)&kp[i];
            *(float4*)&vs[ldr][ldc + i] = *(const float4*)&vp[i];
        }
        __syncthreads();

        float s[16];
#pragma unroll
        for (int j = 0; j < 16; j++) {
            float acc = 0.f;
#pragma unroll
            for (int d = 0; d < HEAD_D; d += 4) {
                float4 k4 = *(const float4*)&ks[j][d];
                acc += q[d + 0] * k4.x;
                acc += q[d + 1] * k4.y;
                acc += q[d + 2] * k4.z;
                acc += q[d + 3] * k4.w;
            }
            s[j] = (j0 + j <= row) ? acc : -1e30f;
        }

        float mc = m;
#pragma unroll
        for (int j = 0; j < 16; j++) mc = fmaxf(mc, s[j]);
        float scaleOld = __expf(m - mc);
        float lsum = 0.f;
#pragma unroll
        for (int j = 0; j < 16; j++) {
            s[j] = __expf(s[j] - mc);
            lsum += s[j];
        }
        l = l * scaleOld + lsum;
#pragma unroll
        for (int d = 0; d < HEAD_D; d++) o[d] *= scaleOld;
#pragma unroll
        for (int j = 0; j < 16; j++) {
            float pj = s[j];
#pragma unroll
            for (int d = 0; d < HEAD_D; d += 4) {
                float4 v4 = *(const float4*)&vs[j][d];
                o[d + 0] += pj * v4.x;
                o[d + 1] += pj * v4.y;
                o[d + 2] += pj * v4.z;
                o[d + 3] += pj * v4.w;
            }
        }
        m = mc;
        __syncthreads();
    }

    float inv = 1.f / l;
    float* op = O + (size_t)row * HIDDEN + h * HEAD_D;
#pragma unroll
    for (int d = 0; d < HEAD_D; d += 4) {
        float4 v4;
        v4.x = o[d + 0] * inv;
        v4.y = o[d + 1] * inv;
        v4.z = o[d + 2] * inv;
        v4.w = o[d + 3] * inv;
        *(float4*)&op[d] = v4;
    }
}

// ---------------------------------------------------------------------------
extern "C" void kernel_launch(void* const* d_in, const int* in_sizes, int n_in,
                              void* d_out, int out_size)
{
    const float* x  = (const float*)d_in[0];
    // d_in[1] = causal_mask (handled analytically)
    const float* Wq = (const float*)d_in[2];
    const float* bq = (const float*)d_in[3];
    const float* Wk = (const float*)d_in[4];
    const float* bk = (const float*)d_in[5];
    const float* Wv = (const float*)d_in[6];
    const float* bv = (const float*)d_in[7];
    const float* Wo = (const float*)d_in[8];
    const float* bo = (const float*)d_in[9];
    float* out = (float*)d_out;

    float* Qb; cudaGetSymbolAddress((void**)&Qb, g_Q);
    float* Kb; cudaGetSymbolAddress((void**)&Kb, g_K);
    float* Vb; cudaGetSymbolAddress((void**)&Vb, g_V);
    float* Ab; cudaGetSymbolAddress((void**)&Ab, g_A);

    dim3 blk(256);
    tf32_gemm_bias_kernel<<<dim3(HIDDEN / 128, SEQ / 128), blk>>>(x, Wq, bq, Qb, SEQ, HIDDEN, HIDDEN);
    tf32_gemm_bias_kernel<<<dim3(KV_DIM / 128, SEQ / 128), blk>>>(x, Wk, bk, Kb, SEQ, KV_DIM, HIDDEN);
    tf32_gemm_bias_kernel<<<dim3(KV_DIM / 128, SEQ / 128), blk>>>(x, Wv, bv, Vb, SEQ, KV_DIM, HIDDEN);
    flash_attn_kernel<<<dim3(SEQ / 64, HEADS), dim3(64)>>>(Qb, Kb, Vb, Ab);
    tf32_gemm_bias_kernel<<<dim3(HIDDEN / 128, SEQ / 128), blk>>>(Ab, Wo, bo, out, SEQ, HIDDEN, HIDDEN);
}

// round 3
// speedup vs baseline: 3.3460x; 1.9991x over previous
#include <cuda_runtime.h>
#include <cuda_bf16.h>
#include <cstdint>

// Problem constants
#define SEQ     2048
#define HIDDEN  2048
#define HEADS   32
#define GROUPS  8
#define HEAD_D  64
#define KV_DIM  512   // GROUPS * HEAD_D
#define QPG     4     // HEADS / GROUPS

// Scratch (device globals: no allocation allowed)
__device__ float g_Q[SEQ * HIDDEN];
__device__ float g_K[SEQ * KV_DIM];
__device__ float g_V[SEQ * KV_DIM];
__device__ float g_A[SEQ * HIDDEN];

__device__ __forceinline__ uint32_t f2tf32(float f) {
    uint32_t u;
    asm("cvt.rna.tf32.f32 %0, %1;\n" : "=r"(u) : "f"(f));
    return u;
}

__device__ __forceinline__ void mma_tf32(float* c, const uint32_t* a, const uint32_t* b) {
    asm volatile(
        "mma.sync.aligned.m16n8k8.row.col.f32.tf32.tf32.f32 "
        "{%0,%1,%2,%3}, {%4,%5,%6,%7}, {%8,%9}, {%0,%1,%2,%3};\n"
        : "+f"(c[0]), "+f"(c[1]), "+f"(c[2]), "+f"(c[3])
        : "r"(a[0]), "r"(a[1]), "r"(a[2]), "r"(a[3]), "r"(b[0]), "r"(b[1]));
}

// ---------------------------------------------------------------------------
// TF32 tensor-core GEMM with bias: C[M,N] = A[M,K] @ B[K,N] + bias[N]
// 128x128 block tile, BK=16, 256 threads (8 warps, 64x32 warp tile).
// Smem holds PRE-CONVERTED tf32 bits; LDG->cvt->STS software pipeline.
// ---------------------------------------------------------------------------
#define AS_LD 20
#define BS_LD 136

__global__ __launch_bounds__(256) void tf32_gemm_bias_kernel(
    const float* __restrict__ A, const float* __restrict__ B,
    const float* __restrict__ bias, float* __restrict__ C,
    int M, int N, int K)
{
    __shared__ uint32_t As[2][128][AS_LD];
    __shared__ uint32_t Bs[2][16][BS_LD];

    const int tid  = threadIdx.x;
    const int warp = tid >> 5;
    const int lane = tid & 31;
    const int gid  = lane >> 2;
    const int tg   = lane & 3;

    const int mBase = (warp & 1) * 64;
    const int nBase = (warp >> 1) * 32;

    const float* Ablk = A + (size_t)blockIdx.y * 128 * K;
    const float* Bblk = B + (size_t)blockIdx.x * 128;

    float acc[4][4][4];
#pragma unroll
    for (int i = 0; i < 4; i++)
#pragma unroll
        for (int j = 0; j < 4; j++)
#pragma unroll
            for (int r = 0; r < 4; r++) acc[i][j][r] = 0.f;

    const int T = K / 16;
    float4 aR[2], bR[2];

    auto ldg_tile = [&](int kt) {
#pragma unroll
        for (int p = 0; p < 2; p++) {
            int s = tid + p * 256;
            aR[p] = *(const float4*)&Ablk[(size_t)(s >> 2) * K + kt + (s & 3) * 4];
            bR[p] = *(const float4*)&Bblk[(size_t)(kt + (s >> 5)) * N + (s & 31) * 4];
        }
    };
    auto sts_tile = [&](int st) {
#pragma unroll
        for (int p = 0; p < 2; p++) {
            int s = tid + p * 256;
            uint4 av = make_uint4(f2tf32(aR[p].x), f2tf32(aR[p].y), f2tf32(aR[p].z), f2tf32(aR[p].w));
            uint4 bv = make_uint4(f2tf32(bR[p].x), f2tf32(bR[p].y), f2tf32(bR[p].z), f2tf32(bR[p].w));
            *(uint4*)&As[st][s >> 2][(s & 3) * 4]  = av;
            *(uint4*)&Bs[st][s >> 5][(s & 31) * 4] = bv;
        }
    };

    ldg_tile(0);
    sts_tile(0);
    __syncthreads();

    for (int t = 0; t < T; t++) {
        if (t + 1 < T) ldg_tile((t + 1) * 16);

        const int st = t & 1;
#pragma unroll
        for (int kc = 0; kc < 16; kc += 8) {
            uint32_t af[4][4];
#pragma unroll
            for (int mt = 0; mt < 4; mt++) {
                int r0 = mBase + mt * 16 + gid;
                af[mt][0] = As[st][r0    ][kc + tg    ];
                af[mt][1] = As[st][r0 + 8][kc + tg    ];
                af[mt][2] = As[st][r0    ][kc + tg + 4];
                af[mt][3] = As[st][r0 + 8][kc + tg + 4];
            }
            uint32_t bf[4][2];
#pragma unroll
            for (int nt = 0; nt < 4; nt++) {
                int c0 = nBase + nt * 8 + gid;
                bf[nt][0] = Bs[st][kc + tg    ][c0];
                bf[nt][1] = Bs[st][kc + tg + 4][c0];
            }
#pragma unroll
            for (int mt = 0; mt < 4; mt++)
#pragma unroll
                for (int nt = 0; nt < 4; nt++)
                    mma_tf32(acc[mt][nt], af[mt], bf[nt]);
        }

        if (t + 1 < T) sts_tile((t + 1) & 1);
        __syncthreads();
    }

#pragma unroll
    for (int mt = 0; mt < 4; mt++) {
#pragma unroll
        for (int nt = 0; nt < 4; nt++) {
            int row = blockIdx.y * 128 + mBase + mt * 16 + gid;
            int col = blockIdx.x * 128 + nBase + nt * 8 + tg * 2;
            float bx = bias[col], by = bias[col + 1];
            *(float2*)&C[(size_t)row * N + col]       = make_float2(acc[mt][nt][0] + bx, acc[mt][nt][1] + by);
            *(float2*)&C[(size_t)(row + 8) * N + col] = make_float2(acc[mt][nt][2] + bx, acc[mt][nt][3] + by);
        }
    }
}

// ---------------------------------------------------------------------------
// Tensor-core flash attention (causal, GQA), tf32 mma.
// grid = (SEQ/64, HEADS), block = 128 (4 warps). Warp w owns query rows
// [w*16, w*16+16) of a 64-row Q tile. K/V staged in smem as tf32 bits;
// P (softmax probs) reuses the K smem region after QK^T.
// ---------------------------------------------------------------------------
#define FPAD 68

__global__ __launch_bounds__(128) void flash_tc_kernel(
    const float* __restrict__ Q, const float* __restrict__ K,
    const float* __restrict__ V, float* __restrict__ O)
{
    __shared__ uint32_t Ks[64][FPAD];   // K tile; reused for P after QK^T
    __shared__ uint32_t Vs[64][FPAD];

    const int qblk = gridDim.x - 1 - blockIdx.x;  // long blocks first
    const int h    = blockIdx.y;
    const int g    = h / QPG;
    const int q0   = qblk * 64;

    const int tid  = threadIdx.x;
    const int warp = tid >> 5;
    const int lane = tid & 31;
    const int gid  = lane >> 2;
    const int tg   = lane & 3;
    const int row0 = warp * 16 + gid;   // local query row (this thread also owns row0+8)

    // Q fragments, converted once, pre-scaled by 1/sqrt(64)
    uint32_t qa[8][4];
    {
        const float* Qb  = Q + (size_t)(q0 + row0) * HIDDEN + h * HEAD_D;
        const float* Qb8 = Qb + 8 * HIDDEN;
#pragma unroll
        for (int ks = 0; ks < 8; ks++) {
            int c = ks * 8 + tg;
            qa[ks][0] = f2tf32(Qb [c]     * 0.125f);
            qa[ks][1] = f2tf32(Qb8[c]     * 0.125f);
            qa[ks][2] = f2tf32(Qb [c + 4] * 0.125f);
            qa[ks][3] = f2tf32(Qb8[c + 4] * 0.125f);
        }
    }

    float accO[8][4];
#pragma unroll
    for (int nt = 0; nt < 8; nt++)
#pragma unroll
        for (int r = 0; r < 4; r++) accO[nt][r] = 0.f;
    float m0 = -1e30f, m1 = -1e30f, l0 = 0.f, l1 = 0.f;

    const int lrow = tid >> 1;          // loader row 0..63
    const int lcol = (tid & 1) * 32;    // loader col half

    for (int t = 0; t <= qblk; t++) {
        const int j0 = t * 64;
        __syncthreads();   // prior tile's PV reads (Ks=Ps, Vs) complete

        // cooperative K/V tile load, converted to tf32
        {
            const float* kp = K + (size_t)(j0 + lrow) * KV_DIM + g * HEAD_D + lcol;
            const float* vp = V + (size_t)(j0 + lrow) * KV_DIM + g * HEAD_D + lcol;
#pragma unroll
            for (int i = 0; i < 8; i++) {
                float4 kv = *(const float4*)&kp[i * 4];
                float4 vv = *(const float4*)&vp[i * 4];
                *(uint4*)&Ks[lrow][lcol + i * 4] =
                    make_uint4(f2tf32(kv.x), f2tf32(kv.y), f2tf32(kv.z), f2tf32(kv.w));
                *(uint4*)&Vs[lrow][lcol + i * 4] =
                    make_uint4(f2tf32(vv.x), f2tf32(vv.y), f2tf32(vv.z), f2tf32(vv.w));
            }
        }
        __syncthreads();

        // S = Q @ K^T for this warp's 16 rows x 64 keys
        float accS[8][4];
#pragma unroll
        for (int nt = 0; nt < 8; nt++)
#pragma unroll
            for (int r = 0; r < 4; r++) accS[nt][r] = 0.f;

#pragma unroll
        for (int ks = 0; ks < 8; ks++) {
#pragma unroll
            for (int nt = 0; nt < 8; nt++) {
                uint32_t b[2] = { Ks[nt * 8 + gid][ks * 8 + tg],
                                  Ks[nt * 8 + gid][ks * 8 + tg + 4] };
                mma_tf32(accS[nt], qa[ks], b);
            }
        }
        __syncthreads();   // all warps done reading Ks -> safe to overwrite with P

        // causal mask (diagonal tile only; j0 == q0 there)
        if (t == qblk) {
#pragma unroll
            for (int nt = 0; nt < 8; nt++) {
                int k0 = nt * 8 + 2 * tg;
                if (k0     > row0)     accS[nt][0] = -1e30f;
                if (k0 + 1 > row0)     accS[nt][1] = -1e30f;
                if (k0     > row0 + 8) accS[nt][2] = -1e30f;
                if (k0 + 1 > row0 + 8) accS[nt][3] = -1e30f;
            }
        }

        // online softmax
        float mx0 = -1e30f, mx1 = -1e30f;
#pragma unroll
        for (int nt = 0; nt < 8; nt++) {
            mx0 = fmaxf(mx0, fmaxf(accS[nt][0], accS[nt][1]));
            mx1 = fmaxf(mx1, fmaxf(accS[nt][2], accS[nt][3]));
        }
        mx0 = fmaxf(mx0, __shfl_xor_sync(0xffffffffu, mx0, 1));
        mx0 = fmaxf(mx0, __shfl_xor_sync(0xffffffffu, mx0, 2));
        mx1 = fmaxf(mx1, __shfl_xor_sync(0xffffffffu, mx1, 1));
        mx1 = fmaxf(mx1, __shfl_xor_sync(0xffffffffu, mx1, 2));

        float mn0 = fmaxf(m0, mx0), mn1 = fmaxf(m1, mx1);
        float sc0 = __expf(m0 - mn0), sc1 = __expf(m1 - mn1);

        float s0 = 0.f, s1 = 0.f;
#pragma unroll
        for (int nt = 0; nt < 8; nt++) {
            accS[nt][0] = __expf(accS[nt][0] - mn0);
            accS[nt][1] = __expf(accS[nt][1] - mn0);
            accS[nt][2] = __expf(accS[nt][2] - mn1);
            accS[nt][3] = __expf(accS[nt][3] - mn1);
            s0 += accS[nt][0] + accS[nt][1];
            s1 += accS[nt][2] + accS[nt][3];
        }
        s0 += __shfl_xor_sync(0xffffffffu, s0, 1);
        s0 += __shfl_xor_sync(0xffffffffu, s0, 2);
        s1 += __shfl_xor_sync(0xffffffffu, s1, 1);
        s1 += __shfl_xor_sync(0xffffffffu, s1, 2);
        l0 = l0 * sc0 + s0;
        l1 = l1 * sc1 + s1;
        m0 = mn0;
        m1 = mn1;

        // write P (tf32) into Ks region — warp-private rows, no cross-warp hazard
#pragma unroll
        for (int nt = 0; nt < 8; nt++) {
            int c = nt * 8 + 2 * tg;
            *(uint2*)&Ks[row0    ][c] = make_uint2(f2tf32(accS[nt][0]), f2tf32(accS[nt][1]));
            *(uint2*)&Ks[row0 + 8][c] = make_uint2(f2tf32(accS[nt][2]), f2tf32(accS[nt][3]));
        }
        __syncwarp();

        // rescale O
#pragma unroll
        for (int nt = 0; nt < 8; nt++) {
            accO[nt][0] *= sc0;
            accO[nt][1] *= sc0;
            accO[nt][2] *= sc1;
            accO[nt][3] *= sc1;
        }

        // O += P @ V
#pragma unroll
        for (int ks = 0; ks < 8; ks++) {
            uint32_t a[4] = { Ks[row0    ][ks * 8 + tg],
                              Ks[row0 + 8][ks * 8 + tg],
                              Ks[row0    ][ks * 8 + tg + 4],
                              Ks[row0 + 8][ks * 8 + tg + 4] };
#pragma unroll
            for (int nt = 0; nt < 8; nt++) {
                uint32_t b[2] = { Vs[ks * 8 + tg    ][nt * 8 + gid],
                                  Vs[ks * 8 + tg + 4][nt * 8 + gid] };
                mma_tf32(accO[nt], a, b);
            }
        }
    }

    // epilogue
    float inv0 = 1.f / l0, inv1 = 1.f / l1;
    float* Ob = O + (size_t)(q0 + row0) * HIDDEN + h * HEAD_D;
#pragma unroll
    for (int nt = 0; nt < 8; nt++) {
        int c = nt * 8 + 2 * tg;
        *(float2*)&Ob[c]              = make_float2(accO[nt][0] * inv0, accO[nt][1] * inv0);
        *(float2*)&Ob[8 * HIDDEN + c] = make_float2(accO[nt][2] * inv1, accO[nt][3] * inv1);
    }
}

// ---------------------------------------------------------------------------
extern "C" void kernel_launch(void* const* d_in, const int* in_sizes, int n_in,
                              void* d_out, int out_size)
{
    const float* x  = (const float*)d_in[0];
    const float* Wq = (const float*)d_in[2];
    const float* bq = (const float*)d_in[3];
    const float* Wk = (const float*)d_in[4];
    const float* bk = (const float*)d_in[5];
    const float* Wv = (const float*)d_in[6];
    const float* bv = (const float*)d_in[7];
    const float* Wo = (const float*)d_in[8];
    const float* bo = (const float*)d_in[9];
    float* out = (float*)d_out;

    float* Qb; cudaGetSymbolAddress((void**)&Qb, g_Q);
    float* Kb; cudaGetSymbolAddress((void**)&Kb, g_K);
    float* Vb; cudaGetSymbolAddress((void**)&Vb, g_V);
    float* Ab; cudaGetSymbolAddress((void**)&Ab, g_A);

    dim3 blk(256);
    tf32_gemm_bias_kernel<<<dim3(HIDDEN / 128, SEQ / 128), blk>>>(x, Wq, bq, Qb, SEQ, HIDDEN, HIDDEN);
    tf32_gemm_bias_kernel<<<dim3(KV_DIM / 128, SEQ / 128), blk>>>(x, Wk, bk, Kb, SEQ, KV_DIM, HIDDEN);
    tf32_gemm_bias_kernel<<<dim3(KV_DIM / 128, SEQ / 128), blk>>>(x, Wv, bv, Vb, SEQ, KV_DIM, HIDDEN);
    flash_tc_kernel<<<dim3(SEQ / 64, HEADS), dim3(128)>>>(Qb, Kb, Vb, Ab);
    tf32_gemm_bias_kernel<<<dim3(HIDDEN / 128, SEQ / 128), blk>>>(Ab, Wo, bo, out, SEQ, HIDDEN, HIDDEN);
}

// round 4
// speedup vs baseline: 4.7732x; 1.4265x over previous
#include <cuda_runtime.h>
#include <cuda_bf16.h>
#include <cstdint>

// Problem constants
#define SEQ     2048
#define HIDDEN  2048
#define HEADS   32
#define GROUPS  8
#define HEAD_D  64
#define KV_DIM  512   // GROUPS * HEAD_D
#define QPG     4     // HEADS / GROUPS

// Scratch (device globals: no allocation allowed)
__device__ float g_Q[SEQ * HIDDEN];
__device__ float g_K[SEQ * KV_DIM];
__device__ float g_V[SEQ * KV_DIM];
__device__ float g_A[SEQ * HIDDEN];

__device__ __forceinline__ uint32_t f2tf32(float f) {
    uint32_t u;
    asm("cvt.rna.tf32.f32 %0, %1;\n" : "=r"(u) : "f"(f));
    return u;
}

__device__ __forceinline__ void mma_tf32(float* c, const uint32_t* a, const uint32_t* b) {
    asm volatile(
        "mma.sync.aligned.m16n8k8.row.col.f32.tf32.tf32.f32 "
        "{%0,%1,%2,%3}, {%4,%5,%6,%7}, {%8,%9}, {%0,%1,%2,%3};\n"
        : "+f"(c[0]), "+f"(c[1]), "+f"(c[2]), "+f"(c[3])
        : "r"(a[0]), "r"(a[1]), "r"(a[2]), "r"(a[3]), "r"(b[0]), "r"(b[1]));
}

// ---------------------------------------------------------------------------
// TF32 GEMM core: C[:,N] tile = A[128,K] @ B[K,128] + bias.  256 threads.
// ---------------------------------------------------------------------------
#define AS_LD 20
#define BS_LD 136

__device__ __forceinline__ void gemm_body(
    const float* __restrict__ A, const float* __restrict__ B,
    const float* __restrict__ bias, float* __restrict__ C,
    int N, int K, int blockRow, int blockCol)
{
    __shared__ uint32_t As[2][128][AS_LD];
    __shared__ uint32_t Bs[2][16][BS_LD];

    const int tid  = threadIdx.x;
    const int warp = tid >> 5;
    const int lane = tid & 31;
    const int gid  = lane >> 2;
    const int tg   = lane & 3;

    const int mBase = (warp & 1) * 64;
    const int nBase = (warp >> 1) * 32;

    const float* Ablk = A + (size_t)blockRow * 128 * K;
    const float* Bblk = B + (size_t)blockCol * 128;

    float acc[4][4][4];
#pragma unroll
    for (int i = 0; i < 4; i++)
#pragma unroll
        for (int j = 0; j < 4; j++)
#pragma unroll
            for (int r = 0; r < 4; r++) acc[i][j][r] = 0.f;

    const int T = K / 16;
    float4 aR[2], bR[2];

    auto ldg_tile = [&](int kt) {
#pragma unroll
        for (int p = 0; p < 2; p++) {
            int s = tid + p * 256;
            aR[p] = *(const float4*)&Ablk[(size_t)(s >> 2) * K + kt + (s & 3) * 4];
            bR[p] = *(const float4*)&Bblk[(size_t)(kt + (s >> 5)) * N + (s & 31) * 4];
        }
    };
    auto sts_tile = [&](int st) {
#pragma unroll
        for (int p = 0; p < 2; p++) {
            int s = tid + p * 256;
            uint4 av = make_uint4(f2tf32(aR[p].x), f2tf32(aR[p].y), f2tf32(aR[p].z), f2tf32(aR[p].w));
            uint4 bv = make_uint4(f2tf32(bR[p].x), f2tf32(bR[p].y), f2tf32(bR[p].z), f2tf32(bR[p].w));
            *(uint4*)&As[st][s >> 2][(s & 3) * 4]  = av;
            *(uint4*)&Bs[st][s >> 5][(s & 31) * 4] = bv;
        }
    };

    ldg_tile(0);
    sts_tile(0);
    __syncthreads();

    for (int t = 0; t < T; t++) {
        if (t + 1 < T) ldg_tile((t + 1) * 16);

        const int st = t & 1;
#pragma unroll
        for (int kc = 0; kc < 16; kc += 8) {
            uint32_t af[4][4];
#pragma unroll
            for (int mt = 0; mt < 4; mt++) {
                int r0 = mBase + mt * 16 + gid;
                af[mt][0] = As[st][r0    ][kc + tg    ];
                af[mt][1] = As[st][r0 + 8][kc + tg    ];
                af[mt][2] = As[st][r0    ][kc + tg + 4];
                af[mt][3] = As[st][r0 + 8][kc + tg + 4];
            }
            uint32_t bf[4][2];
#pragma unroll
            for (int nt = 0; nt < 4; nt++) {
                int c0 = nBase + nt * 8 + gid;
                bf[nt][0] = Bs[st][kc + tg    ][c0];
                bf[nt][1] = Bs[st][kc + tg + 4][c0];
            }
#pragma unroll
            for (int mt = 0; mt < 4; mt++)
#pragma unroll
                for (int nt = 0; nt < 4; nt++)
                    mma_tf32(acc[mt][nt], af[mt], bf[nt]);
        }

        if (t + 1 < T) sts_tile((t + 1) & 1);
        __syncthreads();
    }

#pragma unroll
    for (int mt = 0; mt < 4; mt++) {
#pragma unroll
        for (int nt = 0; nt < 4; nt++) {
            int row = blockRow * 128 + mBase + mt * 16 + gid;
            int col = blockCol * 128 + nBase + nt * 8 + tg * 2;
            float bx = bias[col], by = bias[col + 1];
            *(float2*)&C[(size_t)row * N + col]       = make_float2(acc[mt][nt][0] + bx, acc[mt][nt][1] + by);
            *(float2*)&C[(size_t)(row + 8) * N + col] = make_float2(acc[mt][nt][2] + bx, acc[mt][nt][3] + by);
        }
    }
}

__global__ __launch_bounds__(256) void tf32_gemm_bias_kernel(
    const float* __restrict__ A, const float* __restrict__ B,
    const float* __restrict__ bias, float* __restrict__ C, int N, int K)
{
    gemm_body(A, B, bias, C, N, K, blockIdx.y, blockIdx.x);
}

// Fused QKV projection: grid.x = 16(Q) + 4(K) + 4(V) = 24, grid.y = 16.
__global__ __launch_bounds__(256) void tf32_gemm_qkv_kernel(
    const float* __restrict__ x,
    const float* __restrict__ Wq, const float* __restrict__ bq, float* __restrict__ Qo,
    const float* __restrict__ Wk, const float* __restrict__ bk, float* __restrict__ Ko,
    const float* __restrict__ Wv, const float* __restrict__ bv, float* __restrict__ Vo)
{
    int bx = blockIdx.x;
    if (bx < 16)      gemm_body(x, Wq, bq, Qo, HIDDEN, HIDDEN, blockIdx.y, bx);
    else if (bx < 20) gemm_body(x, Wk, bk, Ko, KV_DIM, HIDDEN, blockIdx.y, bx - 16);
    else              gemm_body(x, Wv, bv, Vo, KV_DIM, HIDDEN, blockIdx.y, bx - 20);
}

// ---------------------------------------------------------------------------
// Tensor-core flash attention v2 (causal, GQA).
// grid = (SEQ/128, HEADS), block = 128 (4 warps). Warp w owns 32 q-rows
// (2 m-tiles of 16). P never touches smem: C-frag -> A-frag via shuffles.
// Ks pad 68 (4*gid+tg banks), Vs pad 72 (8*tg+gid banks): conflict-free.
// ---------------------------------------------------------------------------
#define KPAD 68
#define VPAD 72

__device__ __forceinline__ float shsel(float v0, float v1, int src, int odd) {
    float a = __shfl_sync(0xffffffffu, v0, src);
    float b = __shfl_sync(0xffffffffu, v1, src);
    return odd ? b : a;
}

__global__ __launch_bounds__(128) void flash_tc2_kernel(
    const float* __restrict__ Q, const float* __restrict__ K,
    const float* __restrict__ V, float* __restrict__ O)
{
    __shared__ uint32_t Ks[64][KPAD];
    __shared__ uint32_t Vs[64][VPAD];

    const int qblk = gridDim.x - 1 - blockIdx.x;   // long blocks first
    const int h    = blockIdx.y;
    const int g    = h / QPG;
    const int q0   = qblk * 128;

    const int tid  = threadIdx.x;
    const int warp = tid >> 5;
    const int lane = tid & 31;
    const int gid  = lane >> 2;
    const int tg   = lane & 3;

    // Q fragments (2 m-tiles), converted once, pre-scaled by 1/8
    uint32_t qa[2][8][4];
#pragma unroll
    for (int mt = 0; mt < 2; mt++) {
        const float* QbA = Q + (size_t)(q0 + warp * 32 + mt * 16 + gid) * HIDDEN + h * HEAD_D;
        const float* QbB = QbA + 8 * HIDDEN;
#pragma unroll
        for (int ks = 0; ks < 8; ks++) {
            int c = ks * 8 + tg;
            qa[mt][ks][0] = f2tf32(QbA[c]     * 0.125f);
            qa[mt][ks][1] = f2tf32(QbB[c]     * 0.125f);
            qa[mt][ks][2] = f2tf32(QbA[c + 4] * 0.125f);
            qa[mt][ks][3] = f2tf32(QbB[c + 4] * 0.125f);
        }
    }

    float accO[2][8][4];
#pragma unroll
    for (int mt = 0; mt < 2; mt++)
#pragma unroll
        for (int nt = 0; nt < 8; nt++)
#pragma unroll
            for (int r = 0; r < 4; r++) accO[mt][nt][r] = 0.f;
    float mA[2] = {-1e30f, -1e30f}, mB[2] = {-1e30f, -1e30f};
    float lA[2] = {0.f, 0.f},       lB[2] = {0.f, 0.f};

    const int lrow  = tid & 63;
    const int lhalf = (tid >> 6) * 32;
    const int ntiles = 2 * qblk + 2;
    const int wmin   = q0 + warp * 32;        // min row this warp owns
    const int wmax   = wmin + 31;             // max row this warp owns

    for (int t = 0; t < ntiles; t++) {
        const int j0 = t * 64;
        __syncthreads();   // prior tile's smem reads complete

        {   // cooperative K/V tile load -> tf32 smem
            const float* kp = K + (size_t)(j0 + lrow) * KV_DIM + g * HEAD_D + lhalf;
            const float* vp = V + (size_t)(j0 + lrow) * KV_DIM + g * HEAD_D + lhalf;
#pragma unroll
            for (int i = 0; i < 8; i++) {
                float4 kv = *(const float4*)&kp[i * 4];
                float4 vv = *(const float4*)&vp[i * 4];
                *(uint4*)&Ks[lrow][lhalf + i * 4] =
                    make_uint4(f2tf32(kv.x), f2tf32(kv.y), f2tf32(kv.z), f2tf32(kv.w));
                *(uint4*)&Vs[lrow][lhalf + i * 4] =
                    make_uint4(f2tf32(vv.x), f2tf32(vv.y), f2tf32(vv.z), f2tf32(vv.w));
            }
        }
        __syncthreads();

        if (j0 > wmax) continue;   // tile fully masked for this warp

        // S = Q @ K^T : 32 rows x 64 keys
        float accS[2][8][4];
#pragma unroll
        for (int mt = 0; mt < 2; mt++)
#pragma unroll
            for (int nt = 0; nt < 8; nt++)
#pragma unroll
                for (int r = 0; r < 4; r++) accS[mt][nt][r] = 0.f;

#pragma unroll
        for (int ks = 0; ks < 8; ks++) {
#pragma unroll
            for (int nt = 0; nt < 8; nt++) {
                uint32_t b[2] = { Ks[nt * 8 + gid][ks * 8 + tg],
                                  Ks[nt * 8 + gid][ks * 8 + tg + 4] };
                mma_tf32(accS[0][nt], qa[0][ks], b);
                mma_tf32(accS[1][nt], qa[1][ks], b);
            }
        }

        // causal mask on boundary tiles
        if (j0 + 63 > wmin) {
#pragma unroll
            for (int mt = 0; mt < 2; mt++) {
                int rA = wmin + mt * 16 + gid;
#pragma unroll
                for (int nt = 0; nt < 8; nt++) {
                    int k0 = j0 + nt * 8 + 2 * tg;
                    if (k0     > rA)     accS[mt][nt][0] = -1e30f;
                    if (k0 + 1 > rA)     accS[mt][nt][1] = -1e30f;
                    if (k0     > rA + 8) accS[mt][nt][2] = -1e30f;
                    if (k0 + 1 > rA + 8) accS[mt][nt][3] = -1e30f;
                }
            }
        }

        // online softmax (per m-tile; rows A = regs 0/1, rows B = regs 2/3)
#pragma unroll
        for (int mt = 0; mt < 2; mt++) {
            float mx0 = -1e30f, mx1 = -1e30f;
#pragma unroll
            for (int nt = 0; nt < 8; nt++) {
                mx0 = fmaxf(mx0, fmaxf(accS[mt][nt][0], accS[mt][nt][1]));
                mx1 = fmaxf(mx1, fmaxf(accS[mt][nt][2], accS[mt][nt][3]));
            }
            mx0 = fmaxf(mx0, __shfl_xor_sync(0xffffffffu, mx0, 1));
            mx0 = fmaxf(mx0, __shfl_xor_sync(0xffffffffu, mx0, 2));
            mx1 = fmaxf(mx1, __shfl_xor_sync(0xffffffffu, mx1, 1));
            mx1 = fmaxf(mx1, __shfl_xor_sync(0xffffffffu, mx1, 2));

            float mn0 = fmaxf(mA[mt], mx0), mn1 = fmaxf(mB[mt], mx1);
            float sc0 = __expf(mA[mt] - mn0), sc1 = __expf(mB[mt] - mn1);

            float s0 = 0.f, s1 = 0.f;
#pragma unroll
            for (int nt = 0; nt < 8; nt++) {
                accS[mt][nt][0] = __expf(accS[mt][nt][0] - mn0);
                accS[mt][nt][1] = __expf(accS[mt][nt][1] - mn0);
                accS[mt][nt][2] = __expf(accS[mt][nt][2] - mn1);
                accS[mt][nt][3] = __expf(accS[mt][nt][3] - mn1);
                s0 += accS[mt][nt][0] + accS[mt][nt][1];
                s1 += accS[mt][nt][2] + accS[mt][nt][3];
            }
            s0 += __shfl_xor_sync(0xffffffffu, s0, 1);
            s0 += __shfl_xor_sync(0xffffffffu, s0, 2);
            s1 += __shfl_xor_sync(0xffffffffu, s1, 1);
            s1 += __shfl_xor_sync(0xffffffffu, s1, 2);
            lA[mt] = lA[mt] * sc0 + s0;
            lB[mt] = lB[mt] * sc1 + s1;
            mA[mt] = mn0;
            mB[mt] = mn1;
#pragma unroll
            for (int nt = 0; nt < 8; nt++) {
                accO[mt][nt][0] *= sc0;
                accO[mt][nt][1] *= sc0;
                accO[mt][nt][2] *= sc1;
                accO[mt][nt][3] *= sc1;
            }
        }

        // O += P @ V ; P A-fragments built from accS via shuffles
        const int s0l = gid * 4 + (tg >> 1);
        const int s1l = s0l + 2;
        const int odd = tg & 1;
#pragma unroll
        for (int c = 0; c < 8; c++) {
            uint32_t uaP[2][4];
#pragma unroll
            for (int mt = 0; mt < 2; mt++) {
                uaP[mt][0] = f2tf32(shsel(accS[mt][c][0], accS[mt][c][1], s0l, odd));
                uaP[mt][1] = f2tf32(shsel(accS[mt][c][2], accS[mt][c][3], s0l, odd));
                uaP[mt][2] = f2tf32(shsel(accS[mt][c][0], accS[mt][c][1], s1l, odd));
                uaP[mt][3] = f2tf32(shsel(accS[mt][c][2], accS[mt][c][3], s1l, odd));
            }
#pragma unroll
            for (int nt = 0; nt < 8; nt++) {
                uint32_t b[2] = { Vs[c * 8 + tg    ][nt * 8 + gid],
                                  Vs[c * 8 + tg + 4][nt * 8 + gid] };
                mma_tf32(accO[0][nt], uaP[0], b);
                mma_tf32(accO[1][nt], uaP[1], b);
            }
        }
    }

    // epilogue
#pragma unroll
    for (int mt = 0; mt < 2; mt++) {
        float inv0 = 1.f / lA[mt], inv1 = 1.f / lB[mt];
        float* Ob = O + (size_t)(q0 + warp * 32 + mt * 16 + gid) * HIDDEN + h * HEAD_D;
#pragma unroll
        for (int nt = 0; nt < 8; nt++) {
            int c = nt * 8 + 2 * tg;
            *(float2*)&Ob[c]              = make_float2(accO[mt][nt][0] * inv0, accO[mt][nt][1] * inv0);
            *(float2*)&Ob[8 * HIDDEN + c] = make_float2(accO[mt][nt][2] * inv1, accO[mt][nt][3] * inv1);
        }
    }
}

// ---------------------------------------------------------------------------
extern "C" void kernel_launch(void* const* d_in, const int* in_sizes, int n_in,
                              void* d_out, int out_size)
{
    const float* x  = (const float*)d_in[0];
    const float* Wq = (const float*)d_in[2];
    const float* bq = (const float*)d_in[3];
    const float* Wk = (const float*)d_in[4];
    const float* bk = (const float*)d_in[5];
    const float* Wv = (const float*)d_in[6];
    const float* bv = (const float*)d_in[7];
    const float* Wo = (const float*)d_in[8];
    const float* bo = (const float*)d_in[9];
    float* out = (float*)d_out;

    float* Qb; cudaGetSymbolAddress((void**)&Qb, g_Q);
    float* Kb; cudaGetSymbolAddress((void**)&Kb, g_K);
    float* Vb; cudaGetSymbolAddress((void**)&Vb, g_V);
    float* Ab; cudaGetSymbolAddress((void**)&Ab, g_A);

    tf32_gemm_qkv_kernel<<<dim3(24, SEQ / 128), dim3(256)>>>(
        x, Wq, bq, Qb, Wk, bk, Kb, Wv, bv, Vb);
    flash_tc2_kernel<<<dim3(SEQ / 128, HEADS), dim3(128)>>>(Qb, Kb, Vb, Ab);
    tf32_gemm_bias_kernel<<<dim3(HIDDEN / 128, SEQ / 128), dim3(256)>>>(
        Ab, Wo, bo, out, HIDDEN, HIDDEN);
}